// round 1
// baseline (speedup 1.0000x reference)
#include <cuda_runtime.h>
#include <cuda_bf16.h>
#include <cstddef>

#define NN 50000
#define EE 800000
#define F_IN 128
#define D1 90
#define D2 80
#define D3 50

// ---------------- scratch (static device globals; no allocation) ----------------
__device__ int   g_deg[NN];
__device__ int   g_fill[NN];
__device__ float g_disq[NN];
__device__ int   g_rowptr[NN + 1];
__device__ int   g_csrc[EE];
__device__ float g_cnorm[EE];
__device__ float g_bufA[(size_t)NN * D1];
__device__ float g_bufB[(size_t)NN * D1];
__device__ float g_stats[256];   // [0..D) sum, [128..128+D) sumsq
__device__ float g_scale[128];
__device__ float g_shift[128];

// ---------------- graph build ----------------
__global__ void zero_graph_kernel() {
    int i = blockIdx.x * blockDim.x + threadIdx.x;
    if (i < NN) { g_deg[i] = 0; g_fill[i] = 0; }
}

__global__ void count_kernel(const int* __restrict__ dst) {
    int e = blockIdx.x * blockDim.x + threadIdx.x;
    if (e < EE) atomicAdd(&g_deg[dst[e]], 1);
}

__global__ void disq_kernel() {
    int i = blockIdx.x * blockDim.x + threadIdx.x;
    if (i < NN) g_disq[i] = rsqrtf((float)(g_deg[i] + 1));
}

// single-block exclusive scan of g_deg -> g_rowptr
__global__ void scan_kernel() {
    __shared__ int s[1024];
    __shared__ int carry;
    int tid = threadIdx.x;
    if (tid == 0) carry = 0;
    __syncthreads();
    for (int base = 0; base < NN; base += 1024) {
        int i = base + tid;
        int v = (i < NN) ? g_deg[i] : 0;
        s[tid] = v;
        __syncthreads();
        #pragma unroll
        for (int off = 1; off < 1024; off <<= 1) {
            int t = (tid >= off) ? s[tid - off] : 0;
            __syncthreads();
            s[tid] += t;
            __syncthreads();
        }
        if (i < NN) g_rowptr[i] = carry + s[tid] - v;   // exclusive
        __syncthreads();
        if (tid == 1023) carry += s[1023];
        __syncthreads();
    }
    if (tid == 0) g_rowptr[NN] = carry;  // == EE
}

__global__ void fill_kernel(const int* __restrict__ src, const int* __restrict__ dst) {
    int e = blockIdx.x * blockDim.x + threadIdx.x;
    if (e < EE) {
        int d = dst[e];
        int s = src[e];
        int p = g_rowptr[d] + atomicAdd(&g_fill[d], 1);
        g_csrc[p]  = s;
        g_cnorm[p] = g_disq[s] * g_disq[d];
    }
}

// ---------------- GEMM: Y[N,D] = X[N,K] @ W[K,D] (+ bias) ----------------
template<int K, int D, bool BIAS>
__global__ __launch_bounds__(256)
void gemm_kernel(const float* __restrict__ X, const float* __restrict__ W,
                 const float* __restrict__ Bv, float* __restrict__ Y, int nrows)
{
    constexpr int NC = (D + 31) / 32;
    __shared__ float Ws[K * D];
    int tid = threadIdx.x;
    for (int i = tid; i < K * D; i += 256) Ws[i] = W[i];
    __syncthreads();

    int cx = tid & 31;     // column thread
    int rg = tid >> 5;     // 0..7 row group
    int base = blockIdx.x * 64;

    for (int it = 0; it < 4; it++) {
        int r0 = base + it * 16 + rg * 2;
        if (r0 >= nrows) break;
        bool r1ok = (r0 + 1) < nrows;
        float acc0[NC], acc1[NC];
        #pragma unroll
        for (int j = 0; j < NC; j++) {
            int c = cx + 32 * j;
            float b = 0.0f;
            if (BIAS && c < D) b = Bv[c];
            acc0[j] = b; acc1[j] = b;
        }
        const float* x0 = X + (size_t)r0 * K;
        #pragma unroll 4
        for (int k = 0; k < K; k++) {
            float xv0 = x0[k];
            float xv1 = r1ok ? x0[K + k] : 0.0f;
            #pragma unroll
            for (int j = 0; j < NC; j++) {
                int c = cx + 32 * j;
                if (c < D) {
                    float w = Ws[k * D + c];
                    acc0[j] += xv0 * w;
                    acc1[j] += xv1 * w;
                }
            }
        }
        #pragma unroll
        for (int j = 0; j < NC; j++) {
            int c = cx + 32 * j;
            if (c < D) {
                Y[(size_t)r0 * D + c] = acc0[j];
                if (r1ok) Y[(size_t)(r0 + 1) * D + c] = acc1[j];
            }
        }
    }
}

// ---------------- pull aggregation + bias + relu (D = 90) ----------------
__global__ __launch_bounds__(256)
void aggregate_kernel(const float* __restrict__ T, const float* __restrict__ Bv,
                      float* __restrict__ Y)
{
    constexpr int D = D1;
    int warp = (int)((blockIdx.x * blockDim.x + threadIdx.x) >> 5);
    if (warp >= NN) return;
    int lane = threadIdx.x & 31;
    float dsq = g_disq[warp];
    float selfw = dsq * dsq;

    float acc[3];
    #pragma unroll
    for (int j = 0; j < 3; j++) {
        int c = lane + 32 * j;
        acc[j] = (c < D) ? T[(size_t)warp * D + c] * selfw : 0.0f;
    }
    int beg = g_rowptr[warp];
    int end = g_rowptr[warp + 1];
    for (int e = beg; e < end; e++) {
        int s  = g_csrc[e];
        float w = g_cnorm[e];
        const float* ts = T + (size_t)s * D;
        #pragma unroll
        for (int j = 0; j < 3; j++) {
            int c = lane + 32 * j;
            if (c < D) acc[j] += w * ts[c];
        }
    }
    #pragma unroll
    for (int j = 0; j < 3; j++) {
        int c = lane + 32 * j;
        if (c < D) Y[(size_t)warp * D + c] = fmaxf(acc[j] + Bv[c], 0.0f);
    }
}

// ---------------- batch-norm ----------------
__global__ void zero_stats_kernel() { g_stats[threadIdx.x] = 0.0f; }

template<int D>
__global__ __launch_bounds__(256)
void stats_kernel(const float* __restrict__ Y)
{
    constexpr int NC = (D + 31) / 32;
    __shared__ float ssum[D], ssq[D];
    int tid = threadIdx.x;
    for (int i = tid; i < D; i += 256) { ssum[i] = 0.0f; ssq[i] = 0.0f; }
    __syncthreads();
    int cx = tid & 31, rg = tid >> 5;
    float ls[NC], lq[NC];
    #pragma unroll
    for (int j = 0; j < NC; j++) { ls[j] = 0.0f; lq[j] = 0.0f; }
    for (int r = blockIdx.x * 8 + rg; r < NN; r += gridDim.x * 8) {
        #pragma unroll
        for (int j = 0; j < NC; j++) {
            int c = cx + 32 * j;
            if (c < D) {
                float v = Y[(size_t)r * D + c];
                ls[j] += v; lq[j] += v * v;
            }
        }
    }
    #pragma unroll
    for (int j = 0; j < NC; j++) {
        int c = cx + 32 * j;
        if (c < D) { atomicAdd(&ssum[c], ls[j]); atomicAdd(&ssq[c], lq[j]); }
    }
    __syncthreads();
    for (int i = tid; i < D; i += 256) {
        atomicAdd(&g_stats[i], ssum[i]);
        atomicAdd(&g_stats[128 + i], ssq[i]);
    }
}

__global__ void bn_finalize_kernel(const float* __restrict__ g, const float* __restrict__ b, int D)
{
    int i = threadIdx.x;
    if (i < D) {
        float mean = g_stats[i] * (1.0f / NN);
        float var  = g_stats[128 + i] * (1.0f / NN) - mean * mean;
        float inv  = rsqrtf(var + 1e-5f);
        float sc   = g[i] * inv;
        g_scale[i] = sc;
        g_shift[i] = b[i] - mean * sc;
    }
}

template<int D, bool RELU>
__global__ void bn_apply_kernel(float* __restrict__ Y)
{
    int i = blockIdx.x * blockDim.x + threadIdx.x;
    if (i < NN * D) {
        int c = i % D;
        float v = Y[i] * g_scale[c] + g_shift[c];
        if (RELU) v = fmaxf(v, 0.0f);
        Y[i] = v;
    }
}

// ---------------- final fc3: [N,50] @ [50,1] + b ----------------
__global__ __launch_bounds__(256)
void fc3_kernel(const float* __restrict__ Y, const float* __restrict__ W,
                const float* __restrict__ Bv, float* __restrict__ out)
{
    int warp = (int)((blockIdx.x * blockDim.x + threadIdx.x) >> 5);
    if (warp >= NN) return;
    int lane = threadIdx.x & 31;
    float s = 0.0f;
    if (lane < D3)      s  = Y[(size_t)warp * D3 + lane]      * W[lane];
    if (lane + 32 < D3) s += Y[(size_t)warp * D3 + lane + 32] * W[lane + 32];
    #pragma unroll
    for (int off = 16; off; off >>= 1) s += __shfl_down_sync(0xffffffffu, s, off);
    if (lane == 0) out[warp] = s + Bv[0];
}

// ---------------- launcher ----------------
extern "C" void kernel_launch(void* const* d_in, const int* in_sizes, int n_in,
                              void* d_out, int out_size)
{
    const float* x       = (const float*)d_in[0];
    const int*   ei      = (const int*)  d_in[1];
    const int*   src     = ei;
    const int*   dst     = ei + EE;
    const float* conv1_w = (const float*)d_in[2];
    const float* conv1_b = (const float*)d_in[3];
    const float* convs_w = (const float*)d_in[4];
    const float* convs_b = (const float*)d_in[5];
    const float* bn1_g   = (const float*)d_in[6];
    const float* bn1_b   = (const float*)d_in[7];
    const float* fc1_w   = (const float*)d_in[8];
    const float* fc1_b   = (const float*)d_in[9];
    const float* bn2_g   = (const float*)d_in[10];
    const float* bn2_b   = (const float*)d_in[11];
    const float* fc2_w   = (const float*)d_in[12];
    const float* fc2_b   = (const float*)d_in[13];
    const float* bn3_g   = (const float*)d_in[14];
    const float* bn3_b   = (const float*)d_in[15];
    const float* fc3_w   = (const float*)d_in[16];
    const float* fc3_b   = (const float*)d_in[17];
    float* out = (float*)d_out;

    float *bufA = nullptr, *bufB = nullptr;
    cudaGetSymbolAddress((void**)&bufA, g_bufA);
    cudaGetSymbolAddress((void**)&bufB, g_bufB);

    const int TB = 256;
    const int gN = (NN + TB - 1) / TB;
    const int gE = (EE + TB - 1) / TB;
    const int gWarpN = (NN * 32 + TB - 1) / TB;
    const int gGemm  = (NN + 63) / 64;

    // ---- graph build (per launch; deterministic work) ----
    zero_graph_kernel<<<gN, TB>>>();
    count_kernel<<<gE, TB>>>(dst);
    disq_kernel<<<gN, TB>>>();
    scan_kernel<<<1, 1024>>>();
    fill_kernel<<<gE, TB>>>(src, dst);

    // ---- conv1: relu(Ahat @ (x @ W1) + b1) ----
    gemm_kernel<F_IN, D1, false><<<gGemm, TB>>>(x, conv1_w, nullptr, bufA, NN);
    aggregate_kernel<<<gWarpN, TB>>>(bufA, conv1_b, bufB);

    // ---- 3 more conv layers, each relu then BN(bn1) ----
    for (int l = 0; l < 3; l++) {
        gemm_kernel<D1, D1, false><<<gGemm, TB>>>(bufB, convs_w + (size_t)l * D1 * D1, nullptr, bufA, NN);
        aggregate_kernel<<<gWarpN, TB>>>(bufA, convs_b + (size_t)l * D1, bufB);
        zero_stats_kernel<<<1, 256>>>();
        stats_kernel<D1><<<512, TB>>>(bufB);
        bn_finalize_kernel<<<1, 128>>>(bn1_g, bn1_b, D1);
        bn_apply_kernel<D1, false><<<(NN * D1 + TB - 1) / TB, TB>>>(bufB);
    }

    // ---- fc1 -> bn2 -> relu ----
    gemm_kernel<D1, D2, true><<<gGemm, TB>>>(bufB, fc1_w, fc1_b, bufA, NN);
    zero_stats_kernel<<<1, 256>>>();
    stats_kernel<D2><<<512, TB>>>(bufA);
    bn_finalize_kernel<<<1, 128>>>(bn2_g, bn2_b, D2);
    bn_apply_kernel<D2, true><<<(NN * D2 + TB - 1) / TB, TB>>>(bufA);

    // ---- fc2 -> bn3 -> relu ----
    gemm_kernel<D2, D3, true><<<gGemm, TB>>>(bufA, fc2_w, fc2_b, bufB, NN);
    zero_stats_kernel<<<1, 256>>>();
    stats_kernel<D3><<<512, TB>>>(bufB);
    bn_finalize_kernel<<<1, 128>>>(bn3_g, bn3_b, D3);
    bn_apply_kernel<D3, true><<<(NN * D3 + TB - 1) / TB, TB>>>(bufB);

    // ---- fc3 ----
    fc3_kernel<<<gWarpN, TB>>>(bufB, fc3_w, fc3_b, out);
}

// round 2
// speedup vs baseline: 1.3158x; 1.3158x over previous
#include <cuda_runtime.h>
#include <cuda_bf16.h>
#include <cstddef>

#define NN 50000
#define EE 800000
#define F_IN 128
#define D1 90
#define LD1 96      // padded row stride: 384B = 3 aligned 128B lines
#define D2 80
#define D3 50
#define NSCAN 49    // ceil(50000/1024)

// ---------------- scratch (static device globals; no allocation) ----------------
__device__ int   g_deg[NN];
__device__ int   g_fill[NN];
__device__ float g_disq[NN];
__device__ int   g_rowptr[NN + 1];
__device__ int2  g_edge[EE];                  // {src, norm-as-int-bits}
__device__ int   g_bsum[64];
__device__ int   g_boff[64];
__device__ float g_bufA[(size_t)NN * LD1];
__device__ float g_bufB[(size_t)NN * LD1];
__device__ float g_stats[256];                // [0..D) sum, [128..128+D) sumsq (zeroed by finalize)
__device__ float g_scale[128];
__device__ float g_shift[128];

// ---------------- graph build ----------------
__global__ void zero_deg_kernel() {
    int i = blockIdx.x * blockDim.x + threadIdx.x;
    if (i < NN) g_deg[i] = 0;
}

__global__ void count_kernel(const int* __restrict__ dst) {
    int e = blockIdx.x * blockDim.x + threadIdx.x;
    if (e < EE) atomicAdd(&g_deg[dst[e]], 1);
}

// per-block exclusive scan into rowptr; block totals to g_bsum; fused disq + fill-reset
__global__ __launch_bounds__(1024) void scan_local_kernel() {
    __shared__ int s[1024];
    int tid = threadIdx.x;
    int i = blockIdx.x * 1024 + tid;
    int v = (i < NN) ? g_deg[i] : 0;
    if (i < NN) {
        g_disq[i] = rsqrtf((float)(v + 1));
        g_fill[i] = 0;
    }
    s[tid] = v;
    __syncthreads();
    #pragma unroll
    for (int off = 1; off < 1024; off <<= 1) {
        int t = (tid >= off) ? s[tid - off] : 0;
        __syncthreads();
        s[tid] += t;
        __syncthreads();
    }
    if (i < NN) g_rowptr[i] = s[tid] - v;     // block-local exclusive
    if (tid == 1023) g_bsum[blockIdx.x] = s[1023];
}

__global__ void scan_bsum_kernel() {
    __shared__ int s[64];
    int tid = threadIdx.x;
    int v = (tid < NSCAN) ? g_bsum[tid] : 0;
    s[tid] = v;
    __syncthreads();
    #pragma unroll
    for (int off = 1; off < 64; off <<= 1) {
        int t = (tid >= off) ? s[tid - off] : 0;
        __syncthreads();
        s[tid] += t;
        __syncthreads();
    }
    if (tid < NSCAN) g_boff[tid] = s[tid] - v;
}

__global__ __launch_bounds__(1024) void scan_add_kernel() {
    int i = blockIdx.x * 1024 + threadIdx.x;
    if (i < NN) g_rowptr[i] += g_boff[blockIdx.x];
    if (i == 0) g_rowptr[NN] = EE;
}

__global__ void fill_kernel(const int* __restrict__ src, const int* __restrict__ dst) {
    int e = blockIdx.x * blockDim.x + threadIdx.x;
    if (e < EE) {
        int d = dst[e];
        int s = src[e];
        int p = g_rowptr[d] + atomicAdd(&g_fill[d], 1);
        float nrm = g_disq[s] * g_disq[d];
        g_edge[p] = make_int2(s, __float_as_int(nrm));
    }
}

// ---------------- GEMM: Y[N,D] = XF(X)[N,K] @ W[K,D] (+bias) (+stats) ----------------
// XF: 0=identity, 1=x*scale+shift (BN), 2=relu(x*scale+shift)
template<int K, int LDX, int D, int LDY, int XF, bool BIAS, bool STATS>
__global__ __launch_bounds__(256)
void gemm_kernel(const float* __restrict__ X, const float* __restrict__ W,
                 const float* __restrict__ Bv, float* __restrict__ Y, int nrows)
{
    constexpr int NC = (D + 31) / 32;
    constexpr int SK = (XF > 0) ? K : 1;
    constexpr int SD = STATS ? D : 1;
    __shared__ float Ws[K * D];
    __shared__ float ssc[SK], ssh[SK];
    __shared__ float ssum[SD], ssq[SD];

    int tid = threadIdx.x;
    for (int i = tid; i < K * D; i += 256) Ws[i] = W[i];
    if (XF > 0) for (int i = tid; i < K; i += 256) { ssc[i] = g_scale[i]; ssh[i] = g_shift[i]; }
    if (STATS)  for (int i = tid; i < D; i += 256) { ssum[i] = 0.0f; ssq[i] = 0.0f; }
    __syncthreads();

    int cx = tid & 31;
    int rg = tid >> 5;
    int base = blockIdx.x * 128;
    float lsum[NC], lsq[NC];
    #pragma unroll
    for (int j = 0; j < NC; j++) { lsum[j] = 0.0f; lsq[j] = 0.0f; }

    for (int it = 0; it < 4; it++) {
        int r = base + it * 32 + rg * 4;
        if (r >= nrows) break;
        bool v1 = (r + 1) < nrows, v2 = (r + 2) < nrows, v3 = (r + 3) < nrows;
        float acc[4][NC];
        #pragma unroll
        for (int i = 0; i < 4; i++)
            #pragma unroll
            for (int j = 0; j < NC; j++) {
                int c = cx + 32 * j;
                acc[i][j] = (BIAS && c < D) ? Bv[c] : 0.0f;
            }
        const float* x0 = X + (size_t)r * LDX;
        #pragma unroll 4
        for (int k = 0; k < K; k++) {
            float xv[4];
            xv[0] = x0[k];
            xv[1] = v1 ? x0[LDX + k] : 0.0f;
            xv[2] = v2 ? x0[2 * LDX + k] : 0.0f;
            xv[3] = v3 ? x0[3 * LDX + k] : 0.0f;
            if (XF > 0) {
                float sc = ssc[k], sh = ssh[k];
                #pragma unroll
                for (int i = 0; i < 4; i++) {
                    xv[i] = xv[i] * sc + sh;
                    if (XF == 2) xv[i] = fmaxf(xv[i], 0.0f);
                }
            }
            #pragma unroll
            for (int j = 0; j < NC; j++) {
                int c = cx + 32 * j;
                if (c < D) {
                    float w = Ws[k * D + c];
                    #pragma unroll
                    for (int i = 0; i < 4; i++) acc[i][j] += xv[i] * w;
                }
            }
        }
        #pragma unroll
        for (int j = 0; j < NC; j++) {
            int c = cx + 32 * j;
            if (c < D) {
                Y[(size_t)r * LDY + c] = acc[0][j];
                if (v1) Y[(size_t)(r + 1) * LDY + c] = acc[1][j];
                if (v2) Y[(size_t)(r + 2) * LDY + c] = acc[2][j];
                if (v3) Y[(size_t)(r + 3) * LDY + c] = acc[3][j];
                if (STATS) {
                    float s = acc[0][j], q = acc[0][j] * acc[0][j];
                    if (v1) { s += acc[1][j]; q += acc[1][j] * acc[1][j]; }
                    if (v2) { s += acc[2][j]; q += acc[2][j] * acc[2][j]; }
                    if (v3) { s += acc[3][j]; q += acc[3][j] * acc[3][j]; }
                    lsum[j] += s; lsq[j] += q;
                }
            }
        }
    }
    if (STATS) {
        #pragma unroll
        for (int j = 0; j < NC; j++) {
            int c = cx + 32 * j;
            if (c < D) { atomicAdd(&ssum[c], lsum[j]); atomicAdd(&ssq[c], lsq[j]); }
        }
        __syncthreads();
        if (tid < D) {
            atomicAdd(&g_stats[tid], ssum[tid]);
            atomicAdd(&g_stats[128 + tid], ssq[tid]);
        }
    }
}

// ---------------- pull aggregation + bias + relu (+stats) ----------------
template<bool STATS>
__global__ __launch_bounds__(256)
void aggregate_kernel(const float* __restrict__ T, const float* __restrict__ Bv,
                      float* __restrict__ Y)
{
    constexpr int D = D1;
    constexpr int SD = STATS ? D : 1;
    __shared__ float ssum[SD], ssq[SD];
    int tid = threadIdx.x;
    if (STATS) {
        for (int i = tid; i < D; i += 256) { ssum[i] = 0.0f; ssq[i] = 0.0f; }
        __syncthreads();
    }
    int node = blockIdx.x * 8 + (tid >> 5);
    int lane = tid & 31;
    bool valid = node < NN;
    float vals[3] = {0.0f, 0.0f, 0.0f};

    if (valid) {
        float dsq = g_disq[node];
        float selfw = dsq * dsq;
        const float* tr = T + (size_t)node * LD1;
        float acc[3];
        #pragma unroll
        for (int j = 0; j < 3; j++) {
            int c = lane + 32 * j;
            acc[j] = (c < D) ? tr[c] * selfw : 0.0f;
        }
        int beg = g_rowptr[node];
        int end = g_rowptr[node + 1];
        int e = beg;
        for (; e + 2 <= end; e += 2) {
            int2 e0 = g_edge[e];
            int2 e1 = g_edge[e + 1];
            const float* t0 = T + (size_t)e0.x * LD1;
            const float* t1 = T + (size_t)e1.x * LD1;
            float w0 = __int_as_float(e0.y);
            float w1 = __int_as_float(e1.y);
            #pragma unroll
            for (int j = 0; j < 3; j++) {
                int c = lane + 32 * j;
                if (c < D) {
                    acc[j] += w0 * __ldg(t0 + c);
                    acc[j] += w1 * __ldg(t1 + c);
                }
            }
        }
        if (e < end) {
            int2 e0 = g_edge[e];
            const float* t0 = T + (size_t)e0.x * LD1;
            float w0 = __int_as_float(e0.y);
            #pragma unroll
            for (int j = 0; j < 3; j++) {
                int c = lane + 32 * j;
                if (c < D) acc[j] += w0 * __ldg(t0 + c);
            }
        }
        #pragma unroll
        for (int j = 0; j < 3; j++) {
            int c = lane + 32 * j;
            if (c < D) {
                vals[j] = fmaxf(acc[j] + Bv[c], 0.0f);
                Y[(size_t)node * LD1 + c] = vals[j];
            }
        }
    }
    if (STATS) {
        #pragma unroll
        for (int j = 0; j < 3; j++) {
            int c = lane + 32 * j;
            if (valid && c < D) {
                atomicAdd(&ssum[c], vals[j]);
                atomicAdd(&ssq[c], vals[j] * vals[j]);
            }
        }
        __syncthreads();
        if (tid < D) {
            atomicAdd(&g_stats[tid], ssum[tid]);
            atomicAdd(&g_stats[128 + tid], ssq[tid]);
        }
    }
}

// ---------------- BN finalize (also re-zeroes stats for next use) ----------------
__global__ void bn_finalize_kernel(const float* __restrict__ g, const float* __restrict__ b, int D)
{
    int i = threadIdx.x;
    if (i < D) {
        float mean = g_stats[i] * (1.0f / NN);
        float var  = g_stats[128 + i] * (1.0f / NN) - mean * mean;
        float inv  = rsqrtf(var + 1e-5f);
        float sc   = g[i] * inv;
        g_scale[i] = sc;
        g_shift[i] = b[i] - mean * sc;
        g_stats[i] = 0.0f;
        g_stats[128 + i] = 0.0f;
    }
}

// ---------------- final fc3 with fused relu(bn(x)) ----------------
__global__ __launch_bounds__(256)
void fc3_kernel(const float* __restrict__ Y, const float* __restrict__ W,
                const float* __restrict__ Bv, float* __restrict__ out)
{
    int node = (int)((blockIdx.x * blockDim.x + threadIdx.x) >> 5);
    if (node >= NN) return;
    int lane = threadIdx.x & 31;
    float s = 0.0f;
    if (lane < D3) {
        float v = Y[(size_t)node * D3 + lane];
        v = fmaxf(v * g_scale[lane] + g_shift[lane], 0.0f);
        s = v * W[lane];
    }
    if (lane + 32 < D3) {
        int c = lane + 32;
        float v = Y[(size_t)node * D3 + c];
        v = fmaxf(v * g_scale[c] + g_shift[c], 0.0f);
        s += v * W[c];
    }
    #pragma unroll
    for (int off = 16; off; off >>= 1) s += __shfl_down_sync(0xffffffffu, s, off);
    if (lane == 0) out[node] = s + Bv[0];
}

// ---------------- launcher ----------------
extern "C" void kernel_launch(void* const* d_in, const int* in_sizes, int n_in,
                              void* d_out, int out_size)
{
    const float* x       = (const float*)d_in[0];
    const int*   ei      = (const int*)  d_in[1];
    const int*   src     = ei;
    const int*   dst     = ei + EE;
    const float* conv1_w = (const float*)d_in[2];
    const float* conv1_b = (const float*)d_in[3];
    const float* convs_w = (const float*)d_in[4];
    const float* convs_b = (const float*)d_in[5];
    const float* bn1_g   = (const float*)d_in[6];
    const float* bn1_b   = (const float*)d_in[7];
    const float* fc1_w   = (const float*)d_in[8];
    const float* fc1_b   = (const float*)d_in[9];
    const float* bn2_g   = (const float*)d_in[10];
    const float* bn2_b   = (const float*)d_in[11];
    const float* fc2_w   = (const float*)d_in[12];
    const float* fc2_b   = (const float*)d_in[13];
    const float* bn3_g   = (const float*)d_in[14];
    const float* bn3_b   = (const float*)d_in[15];
    const float* fc3_w   = (const float*)d_in[16];
    const float* fc3_b   = (const float*)d_in[17];
    float* out = (float*)d_out;

    float *bufA = nullptr, *bufB = nullptr;
    cudaGetSymbolAddress((void**)&bufA, g_bufA);
    cudaGetSymbolAddress((void**)&bufB, g_bufB);

    const int TB = 256;
    const int gN = (NN + TB - 1) / TB;
    const int gE = (EE + TB - 1) / TB;
    const int gWarpN = (NN * 32 + TB - 1) / TB;   // 1 warp per node
    const int gGemm  = (NN + 127) / 128;

    // ---- graph build ----
    zero_deg_kernel<<<gN, TB>>>();
    count_kernel<<<gE, TB>>>(dst);
    scan_local_kernel<<<NSCAN, 1024>>>();
    scan_bsum_kernel<<<1, 64>>>();
    scan_add_kernel<<<NSCAN, 1024>>>();
    fill_kernel<<<gE, TB>>>(src, dst);

    // ---- conv1: relu(Ahat @ (x @ W1) + b1) ----
    gemm_kernel<F_IN, F_IN, D1, LD1, 0, false, false><<<gGemm, TB>>>(x, conv1_w, nullptr, bufA, NN);
    aggregate_kernel<false><<<gWarpN, TB>>>(bufA, conv1_b, bufB);

    // ---- conv layer 2 (input has no BN), then BN ----
    gemm_kernel<D1, LD1, D1, LD1, 0, false, false><<<gGemm, TB>>>(bufB, convs_w, nullptr, bufA, NN);
    aggregate_kernel<true><<<gWarpN, TB>>>(bufA, convs_b, bufB);
    bn_finalize_kernel<<<1, 128>>>(bn1_g, bn1_b, D1);

    // ---- conv layers 3,4 (BN applied to input inside gemm), then BN ----
    for (int l = 1; l < 3; l++) {
        gemm_kernel<D1, LD1, D1, LD1, 1, false, false><<<gGemm, TB>>>(
            bufB, convs_w + (size_t)l * D1 * D1, nullptr, bufA, NN);
        aggregate_kernel<true><<<gWarpN, TB>>>(bufA, convs_b + (size_t)l * D1, bufB);
        bn_finalize_kernel<<<1, 128>>>(bn1_g, bn1_b, D1);
    }

    // ---- fc1 (BN input) -> stats -> bn2 ----
    gemm_kernel<D1, LD1, D2, D2, 1, true, true><<<gGemm, TB>>>(bufB, fc1_w, fc1_b, bufA, NN);
    bn_finalize_kernel<<<1, 128>>>(bn2_g, bn2_b, D2);

    // ---- fc2 (relu(BN) input) -> stats -> bn3 ----
    gemm_kernel<D2, D2, D3, D3, 2, true, true><<<gGemm, TB>>>(bufA, fc2_w, fc2_b, bufB, NN);
    bn_finalize_kernel<<<1, 128>>>(bn3_g, bn3_b, D3);

    // ---- fc3 (relu(BN) input, fused) ----
    fc3_kernel<<<gWarpN, TB>>>(bufB, fc3_w, fc3_b, out);
}

// round 3
// speedup vs baseline: 1.3575x; 1.0317x over previous
#include <cuda_runtime.h>
#include <cuda_bf16.h>
#include <cstddef>

#define NN 50000
#define EE 800000
#define F_IN 128
#define D1 90
#define LD1 96      // padded row stride: 384B = 3 aligned 128B lines
#define D2 80
#define D3 50
#define NSCAN 49    // ceil(50000/1024)

// ---------------- scratch (static device globals; no allocation) ----------------
__device__ int   g_deg[NN];
__device__ int   g_fill[NN];
__device__ float g_disq[NN];
__device__ int   g_rowptr[NN + 1];
__device__ int2  g_edge[EE];                  // {src, norm-as-int-bits}
__device__ int   g_bsum[64];
__device__ int   g_boff[64];
__device__ float g_bufA[(size_t)NN * LD1];
__device__ float g_bufB[(size_t)NN * LD1];
__device__ float g_stats[256];                // [0..D) sum, [128..128+D) sumsq (zeroed by finalize)
__device__ float g_scale[128];
__device__ float g_shift[128];

// ---------------- graph build ----------------
__global__ void zero_deg_kernel() {
    int i = blockIdx.x * blockDim.x + threadIdx.x;
    if (i < NN) g_deg[i] = 0;
}

__global__ void count_kernel(const int* __restrict__ dst) {
    int e = blockIdx.x * blockDim.x + threadIdx.x;
    if (e < EE) atomicAdd(&g_deg[dst[e]], 1);
}

// per-block exclusive scan into rowptr; block totals to g_bsum; fused disq + fill-reset
__global__ __launch_bounds__(1024) void scan_local_kernel() {
    __shared__ int s[1024];
    int tid = threadIdx.x;
    int i = blockIdx.x * 1024 + tid;
    int v = (i < NN) ? g_deg[i] : 0;
    if (i < NN) {
        g_disq[i] = rsqrtf((float)(v + 1));
        g_fill[i] = 0;
    }
    s[tid] = v;
    __syncthreads();
    #pragma unroll
    for (int off = 1; off < 1024; off <<= 1) {
        int t = (tid >= off) ? s[tid - off] : 0;
        __syncthreads();
        s[tid] += t;
        __syncthreads();
    }
    if (i < NN) g_rowptr[i] = s[tid] - v;     // block-local exclusive
    if (tid == 1023) g_bsum[blockIdx.x] = s[1023];
}

__global__ void scan_bsum_kernel() {
    __shared__ int s[64];
    int tid = threadIdx.x;
    int v = (tid < NSCAN) ? g_bsum[tid] : 0;
    s[tid] = v;
    __syncthreads();
    #pragma unroll
    for (int off = 1; off < 64; off <<= 1) {
        int t = (tid >= off) ? s[tid - off] : 0;
        __syncthreads();
        s[tid] += t;
        __syncthreads();
    }
    if (tid < NSCAN) g_boff[tid] = s[tid] - v;
}

__global__ __launch_bounds__(1024) void scan_add_kernel() {
    int i = blockIdx.x * 1024 + threadIdx.x;
    if (i < NN) g_rowptr[i] += g_boff[blockIdx.x];
    if (i == 0) g_rowptr[NN] = EE;
}

__global__ void fill_kernel(const int* __restrict__ src, const int* __restrict__ dst) {
    int e = blockIdx.x * blockDim.x + threadIdx.x;
    if (e < EE) {
        int d = dst[e];
        int s = src[e];
        int p = g_rowptr[d] + atomicAdd(&g_fill[d], 1);
        float nrm = g_disq[s] * g_disq[d];
        g_edge[p] = make_int2(s, __float_as_int(nrm));
    }
}

// ---------------- GEMM: Y[N,D] = XF(X)[N,K] @ W[K,D] (+bias) (+stats) ----------------
// XF: 0=identity, 1=x*scale+shift (BN), 2=relu(x*scale+shift)
// K padded up to KP (mult of 4); W rows [K,KP) zeroed; X rows must be readable to KP (LDX>=KP).
template<int K, int LDX, int D, int LDY, int XF, bool BIAS, bool STATS>
__global__ __launch_bounds__(256)
void gemm_kernel(const float* __restrict__ X, const float* __restrict__ W,
                 const float* __restrict__ Bv, float* __restrict__ Y, int nrows)
{
    constexpr int NC = (D + 31) / 32;
    constexpr int KP = (K + 3) & ~3;
    constexpr int SK = (XF > 0) ? KP : 1;
    constexpr int SD = STATS ? D : 1;
    __shared__ float Ws[KP * D];
    __shared__ float ssc[SK], ssh[SK];
    __shared__ float ssum[SD], ssq[SD];

    int tid = threadIdx.x;
    for (int i = tid; i < KP * D; i += 256) Ws[i] = (i < K * D) ? W[i] : 0.0f;
    if (XF > 0) for (int i = tid; i < KP; i += 256) {
        ssc[i] = (i < K) ? g_scale[i] : 0.0f;
        ssh[i] = (i < K) ? g_shift[i] : 0.0f;
    }
    if (STATS)  for (int i = tid; i < D; i += 256) { ssum[i] = 0.0f; ssq[i] = 0.0f; }
    __syncthreads();

    int cx = tid & 31;
    int rg = tid >> 5;
    int base = blockIdx.x * 128;
    float lsum[NC], lsq[NC];
    #pragma unroll
    for (int j = 0; j < NC; j++) { lsum[j] = 0.0f; lsq[j] = 0.0f; }

    for (int it = 0; it < 4; it++) {
        int r = base + it * 32 + rg * 4;
        if (r >= nrows) break;
        bool vld[4];
        vld[0] = true;
        vld[1] = (r + 1) < nrows; vld[2] = (r + 2) < nrows; vld[3] = (r + 3) < nrows;
        float acc[4][NC];
        #pragma unroll
        for (int i = 0; i < 4; i++)
            #pragma unroll
            for (int j = 0; j < NC; j++) {
                int c = cx + 32 * j;
                acc[i][j] = (BIAS && c < D) ? Bv[c] : 0.0f;
            }
        const float* x0 = X + (size_t)r * LDX;
        #pragma unroll 2
        for (int k4 = 0; k4 < KP; k4 += 4) {
            float xs[4][4];
            #pragma unroll
            for (int i = 0; i < 4; i++) {
                float4 t = vld[i] ? *(const float4*)(x0 + (size_t)i * LDX + k4)
                                  : make_float4(0.f, 0.f, 0.f, 0.f);
                xs[i][0] = t.x; xs[i][1] = t.y; xs[i][2] = t.z; xs[i][3] = t.w;
            }
            if (XF > 0) {
                #pragma unroll
                for (int kk = 0; kk < 4; kk++) {
                    float sc = ssc[k4 + kk], sh = ssh[k4 + kk];
                    #pragma unroll
                    for (int i = 0; i < 4; i++) {
                        float v = xs[i][kk] * sc + sh;
                        if (XF == 2) v = fmaxf(v, 0.0f);
                        xs[i][kk] = v;
                    }
                }
            }
            #pragma unroll
            for (int kk = 0; kk < 4; kk++) {
                #pragma unroll
                for (int j = 0; j < NC; j++) {
                    int c = cx + 32 * j;
                    float w = (c < D) ? Ws[(k4 + kk) * D + c] : 0.0f;
                    #pragma unroll
                    for (int i = 0; i < 4; i++) acc[i][j] += xs[i][kk] * w;
                }
            }
        }
        #pragma unroll
        for (int j = 0; j < NC; j++) {
            int c = cx + 32 * j;
            if (c < D) {
                #pragma unroll
                for (int i = 0; i < 4; i++)
                    if (vld[i]) Y[(size_t)(r + i) * LDY + c] = acc[i][j];
                if (STATS) {
                    float s = 0.0f, q = 0.0f;
                    #pragma unroll
                    for (int i = 0; i < 4; i++)
                        if (vld[i]) { s += acc[i][j]; q += acc[i][j] * acc[i][j]; }
                    lsum[j] += s; lsq[j] += q;
                }
            } else if (c < LDY) {
                #pragma unroll
                for (int i = 0; i < 4; i++)
                    if (vld[i]) Y[(size_t)(r + i) * LDY + c] = 0.0f;   // keep padding clean
            }
        }
    }
    if (STATS) {
        #pragma unroll
        for (int j = 0; j < NC; j++) {
            int c = cx + 32 * j;
            if (c < D) { atomicAdd(&ssum[c], lsum[j]); atomicAdd(&ssq[c], lsq[j]); }
        }
        __syncthreads();
        if (tid < D) {
            atomicAdd(&g_stats[tid], ssum[tid]);
            atomicAdd(&g_stats[128 + tid], ssq[tid]);
        }
    }
}

// ---------------- pull aggregation + bias + relu (+stats), float4 lanes ----------------
// lane l (<24) owns columns [4l, 4l+4); rows stride LD1=96 floats (16B aligned).
template<bool STATS>
__global__ __launch_bounds__(256)
void aggregate_kernel(const float* __restrict__ T, const float* __restrict__ Bv,
                      float* __restrict__ Y)
{
    constexpr int D = D1;
    constexpr int SD = STATS ? D : 1;
    __shared__ float ssum[SD], ssq[SD];
    int tid = threadIdx.x;
    if (STATS) {
        for (int i = tid; i < D; i += 256) { ssum[i] = 0.0f; ssq[i] = 0.0f; }
        __syncthreads();
    }
    int node = blockIdx.x * 8 + (tid >> 5);
    int lane = tid & 31;
    int c0 = lane * 4;
    bool act = (node < NN) && (lane < 24);
    float vals[4] = {0.0f, 0.0f, 0.0f, 0.0f};

    if (act) {
        float dsq = g_disq[node];
        float selfw = dsq * dsq;
        float4 t0 = *(const float4*)(T + (size_t)node * LD1 + c0);
        float4 acc = make_float4(t0.x * selfw, t0.y * selfw, t0.z * selfw, t0.w * selfw);

        int beg = g_rowptr[node];
        int end = g_rowptr[node + 1];
        int e = beg;
        for (; e + 2 <= end; e += 2) {
            int2 e0 = g_edge[e];
            int2 e1 = g_edge[e + 1];
            float4 ta = *(const float4*)(T + (size_t)e0.x * LD1 + c0);
            float4 tb = *(const float4*)(T + (size_t)e1.x * LD1 + c0);
            float w0 = __int_as_float(e0.y);
            float w1 = __int_as_float(e1.y);
            acc.x += w0 * ta.x; acc.y += w0 * ta.y; acc.z += w0 * ta.z; acc.w += w0 * ta.w;
            acc.x += w1 * tb.x; acc.y += w1 * tb.y; acc.z += w1 * tb.z; acc.w += w1 * tb.w;
        }
        if (e < end) {
            int2 e0 = g_edge[e];
            float4 ta = *(const float4*)(T + (size_t)e0.x * LD1 + c0);
            float w0 = __int_as_float(e0.y);
            acc.x += w0 * ta.x; acc.y += w0 * ta.y; acc.z += w0 * ta.z; acc.w += w0 * ta.w;
        }
        float am[4] = {acc.x, acc.y, acc.z, acc.w};
        #pragma unroll
        for (int m = 0; m < 4; m++) {
            int c = c0 + m;
            vals[m] = (c < D) ? fmaxf(am[m] + Bv[c], 0.0f) : 0.0f;
        }
        *(float4*)(Y + (size_t)node * LD1 + c0) = make_float4(vals[0], vals[1], vals[2], vals[3]);
    }
    if (STATS) {
        #pragma unroll
        for (int m = 0; m < 4; m++) {
            int c = c0 + m;
            if (act && c < D) {
                atomicAdd(&ssum[c], vals[m]);
                atomicAdd(&ssq[c], vals[m] * vals[m]);
            }
        }
        __syncthreads();
        if (tid < D) {
            atomicAdd(&g_stats[tid], ssum[tid]);
            atomicAdd(&g_stats[128 + tid], ssq[tid]);
        }
    }
}

// ---------------- BN finalize (also re-zeroes stats for next use) ----------------
__global__ void bn_finalize_kernel(const float* __restrict__ g, const float* __restrict__ b, int D)
{
    int i = threadIdx.x;
    if (i < D) {
        float mean = g_stats[i] * (1.0f / NN);
        float var  = g_stats[128 + i] * (1.0f / NN) - mean * mean;
        float inv  = rsqrtf(var + 1e-5f);
        float sc   = g[i] * inv;
        g_scale[i] = sc;
        g_shift[i] = b[i] - mean * sc;
        g_stats[i] = 0.0f;
        g_stats[128 + i] = 0.0f;
    }
}

// ---------------- final fc3 with fused relu(bn(x)) ----------------
__global__ __launch_bounds__(256)
void fc3_kernel(const float* __restrict__ Y, const float* __restrict__ W,
                const float* __restrict__ Bv, float* __restrict__ out)
{
    int node = (int)((blockIdx.x * blockDim.x + threadIdx.x) >> 5);
    if (node >= NN) return;
    int lane = threadIdx.x & 31;
    float s = 0.0f;
    if (lane < D3) {
        float v = Y[(size_t)node * D3 + lane];
        v = fmaxf(v * g_scale[lane] + g_shift[lane], 0.0f);
        s = v * W[lane];
    }
    if (lane + 32 < D3) {
        int c = lane + 32;
        float v = Y[(size_t)node * D3 + c];
        v = fmaxf(v * g_scale[c] + g_shift[c], 0.0f);
        s += v * W[c];
    }
    #pragma unroll
    for (int off = 16; off; off >>= 1) s += __shfl_down_sync(0xffffffffu, s, off);
    if (lane == 0) out[node] = s + Bv[0];
}

// ---------------- launcher ----------------
extern "C" void kernel_launch(void* const* d_in, const int* in_sizes, int n_in,
                              void* d_out, int out_size)
{
    const float* x       = (const float*)d_in[0];
    const int*   ei      = (const int*)  d_in[1];
    const int*   src     = ei;
    const int*   dst     = ei + EE;
    const float* conv1_w = (const float*)d_in[2];
    const float* conv1_b = (const float*)d_in[3];
    const float* convs_w = (const float*)d_in[4];
    const float* convs_b = (const float*)d_in[5];
    const float* bn1_g   = (const float*)d_in[6];
    const float* bn1_b   = (const float*)d_in[7];
    const float* fc1_w   = (const float*)d_in[8];
    const float* fc1_b   = (const float*)d_in[9];
    const float* bn2_g   = (const float*)d_in[10];
    const float* bn2_b   = (const float*)d_in[11];
    const float* fc2_w   = (const float*)d_in[12];
    const float* fc2_b   = (const float*)d_in[13];
    const float* bn3_g   = (const float*)d_in[14];
    const float* bn3_b   = (const float*)d_in[15];
    const float* fc3_w   = (const float*)d_in[16];
    const float* fc3_b   = (const float*)d_in[17];
    float* out = (float*)d_out;

    float *bufA = nullptr, *bufB = nullptr;
    cudaGetSymbolAddress((void**)&bufA, g_bufA);
    cudaGetSymbolAddress((void**)&bufB, g_bufB);

    // side stream + events for fork/join under graph capture (created once; host objects only)
    static cudaStream_t s2 = nullptr;
    static cudaEvent_t  evFork = nullptr, evJoin = nullptr;
    if (!s2) {
        cudaStreamCreateWithFlags(&s2, cudaStreamNonBlocking);
        cudaEventCreateWithFlags(&evFork, cudaEventDisableTiming);
        cudaEventCreateWithFlags(&evJoin, cudaEventDisableTiming);
    }

    const int TB = 256;
    const int gN = (NN + TB - 1) / TB;
    const int gE = (EE + TB - 1) / TB;
    const int gWarpN = (NN + 7) / 8;              // 8 nodes (warps) per block
    const int gGemm  = (NN + 127) / 128;

    // ---- fork: conv1 dense transform runs concurrently with graph build ----
    cudaEventRecord(evFork, 0);
    cudaStreamWaitEvent(s2, evFork, 0);
    gemm_kernel<F_IN, F_IN, D1, LD1, 0, false, false><<<gGemm, TB, 0, s2>>>(x, conv1_w, nullptr, bufA, NN);
    cudaEventRecord(evJoin, s2);

    // ---- graph build (default stream) ----
    zero_deg_kernel<<<gN, TB>>>();
    count_kernel<<<gE, TB>>>(dst);
    scan_local_kernel<<<NSCAN, 1024>>>();
    scan_bsum_kernel<<<1, 64>>>();
    scan_add_kernel<<<NSCAN, 1024>>>();
    fill_kernel<<<gE, TB>>>(src, dst);

    // ---- join, then aggregate conv1 ----
    cudaStreamWaitEvent(0, evJoin, 0);
    aggregate_kernel<false><<<gWarpN, TB>>>(bufA, conv1_b, bufB);

    // ---- conv layer 2 (input has no BN), then BN ----
    gemm_kernel<D1, LD1, D1, LD1, 0, false, false><<<gGemm, TB>>>(bufB, convs_w, nullptr, bufA, NN);
    aggregate_kernel<true><<<gWarpN, TB>>>(bufA, convs_b, bufB);
    bn_finalize_kernel<<<1, 128>>>(bn1_g, bn1_b, D1);

    // ---- conv layers 3,4 (BN applied to input inside gemm), then BN ----
    for (int l = 1; l < 3; l++) {
        gemm_kernel<D1, LD1, D1, LD1, 1, false, false><<<gGemm, TB>>>(
            bufB, convs_w + (size_t)l * D1 * D1, nullptr, bufA, NN);
        aggregate_kernel<true><<<gWarpN, TB>>>(bufA, convs_b + (size_t)l * D1, bufB);
        bn_finalize_kernel<<<1, 128>>>(bn1_g, bn1_b, D1);
    }

    // ---- fc1 (BN input) -> stats -> bn2 ----
    gemm_kernel<D1, LD1, D2, D2, 1, true, true><<<gGemm, TB>>>(bufB, fc1_w, fc1_b, bufA, NN);
    bn_finalize_kernel<<<1, 128>>>(bn2_g, bn2_b, D2);

    // ---- fc2 (relu(BN) input) -> stats -> bn3 ----
    gemm_kernel<D2, D2, D3, D3, 2, true, true><<<gGemm, TB>>>(bufA, fc2_w, fc2_b, bufB, NN);
    bn_finalize_kernel<<<1, 128>>>(bn3_g, bn3_b, D3);

    // ---- fc3 (relu(BN) input, fused) ----
    fc3_kernel<<<(NN * 32 + TB - 1) / TB, TB>>>(bufB, fc3_w, fc3_b, out);
}